// round 3
// baseline (speedup 1.0000x reference)
#include <cuda_runtime.h>

#define VOCAB  8000
#define HIDDEN 256
#define BATCH  32
#define SEQ    256
#define OUT_MAIN (SEQ * BATCH * VOCAB)   // 65,536,000 floats

typedef unsigned long long ull;

// ---------------- scratch (__device__ globals: no allocs allowed) ----------
__device__ float  g_Y[SEQ * BATCH * HIDDEN];   // (t*BATCH + b)*HIDDEN + h
__device__ float4 g_Wre[16 * 1024];            // W_hh, thread-major float4 layout

// ---------------- packed f32x2 helpers (sm_103a) ---------------------------
__device__ __forceinline__ void ffma2(ull& d, ull a, ull b) {
    asm("fma.rn.f32x2 %0, %1, %2, %0;" : "+l"(d) : "l"(a), "l"(b));
}
__device__ __forceinline__ ull pack2(float x, float y) {
    ull r; asm("mov.b64 %0, {%1, %2};" : "=l"(r) : "f"(x), "f"(y)); return r;
}
__device__ __forceinline__ float2 unpack2(ull v) {
    float2 r; asm("mov.b64 {%0, %1}, %2;" : "=f"(r.x), "=f"(r.y) : "l"(v)); return r;
}
union F4U { float4 f4; ulonglong2 u2; };

// ---------------- prep: reshuffle W_hh into thread-major layout ------------
// Thread t of the RNN CTA owns row j = t&255, k-slice s = t>>8 (64 floats).
// g_Wre[i*1024 + t] = W_hh[j, s*64 + 4i .. 4i+3]  (i < 16)
__global__ void prep_kernel(const float* __restrict__ W_hh) {
    int g   = blockIdx.x * blockDim.x + threadIdx.x;  // 0..16383
    int i   = g >> 10;
    int tid = g & 1023;
    int j   = tid & 255;
    int s   = tid >> 8;
    g_Wre[i * 1024 + tid] =
        *reinterpret_cast<const float4*>(&W_hh[j * HIDDEN + s * 64 + 4 * i]);
}

// ---------------- recurrence (fused embedding gather) ----------------------
// One CTA per batch element. 1024 threads: (row j, slice s). Per step:
//   acc_js = sum_{k in slice s} h[k] * W_hh[j,k]   (packed f32x2)
//   reduce 4 slices in smem, add x_t = W_ih[j, X[b,t]] + b_ih[j] + b_hh[j],
//   tanh, write h back to smem and Y to global.
__global__ __launch_bounds__(1024, 1) void rnn_kernel(
    const int*   __restrict__ X,
    const float* __restrict__ h0,
    const float* __restrict__ W_ih,
    const float* __restrict__ b_ih,
    const float* __restrict__ b_hh,
    float*       __restrict__ hlast,
    int write_hlast)
{
    __shared__ __align__(16) float h_sh[HIDDEN];
    __shared__ float psum[4 * HIDDEN];
    __shared__ int   x_sh[SEQ];

    const int b   = blockIdx.x;
    const int tid = threadIdx.x;
    const int j   = tid & 255;
    const int s   = tid >> 8;

    float bias = 0.f;
    if (s == 0) bias = b_hh[j] + b_ih[j];
    if (tid < HIDDEN) h_sh[tid] = h0[b * HIDDEN + tid];
    if (tid < SEQ)    x_sh[tid] = X[b * SEQ + tid];
    __syncthreads();

    const float*  Wih_row = W_ih + (size_t)j * VOCAB;
    const float4* wre     = g_Wre + tid;
    float*        Yb      = g_Y + b * HIDDEN;

    for (int t = 0; t < SEQ; ++t) {
        // Embedding gather for this step — issued before the FMA loop so its
        // L2 latency hides behind 32 FMA2s + the reduction barrier.
        float xv = 0.f;
        if (s == 0) xv = __ldg(&Wih_row[x_sh[t]]);

        ull acc = 0ULL;
        const ulonglong2* h2 = reinterpret_cast<const ulonglong2*>(h_sh + s * 64);
        #pragma unroll
        for (int i = 0; i < 16; ++i) {
            ulonglong2 hv = h2[i];          // 4 h values (broadcast LDS.128)
            F4U u; u.f4 = wre[i * 1024];    // 4 weights (L1-resident LDG.128)
            ffma2(acc, hv.x, u.u2.x);
            ffma2(acc, hv.y, u.u2.y);
        }
        float2 a2 = unpack2(acc);
        psum[s * HIDDEN + j] = a2.x + a2.y;
        __syncthreads();
        if (s == 0) {
            float v = psum[j] + psum[HIDDEN + j] + psum[2 * HIDDEN + j] +
                      psum[3 * HIDDEN + j] + xv + bias;
            float hn = tanhf(v);
            h_sh[j] = hn;
            Yb[(size_t)t * BATCH * HIDDEN + j] = hn;
        }
        __syncthreads();
    }
    if (write_hlast && tid < HIDDEN) hlast[b * HIDDEN + tid] = h_sh[tid];
}

// ---------------- output GEMM: C = Y @ W_out^T + b_out --------------------
// M=8192, N=8000, K=256. BM=128, BN=64, BK=32, 256 threads, 8x4 micro-tile,
// inner product done with packed fma.rn.f32x2 (rows paired, cols broadcast).
#define GBM 128
#define GBN 64
#define GBK 32
#define ASTR 36   // As row stride (pad keeps float4 alignment, 2-way max)
#define BSTR 68   // Bs row stride

__global__ __launch_bounds__(256) void gemm_kernel(
    const float* __restrict__ W_out,
    const float* __restrict__ b_out,
    float*       __restrict__ C)
{
    __shared__ float As[GBM * ASTR];   // [row][k]
    __shared__ float Bs[GBK * BSTR];   // [k][col]

    const int tid = threadIdx.x;
    const int tc  = tid & 15;          // 16 col-groups of 4
    const int tr  = tid >> 4;          // 16 row-groups of 8
    const int rb  = blockIdx.y * GBM;
    const int cb  = blockIdx.x * GBN;
    const int k4  = (tid & 7) * 4;     // loader k offset
    const int rr  = tid >> 3;          // loader row/col 0..31

    ull acc[16];
    #pragma unroll
    for (int i = 0; i < 16; ++i) acc[i] = 0ULL;

    const float* A = g_Y;

    for (int kc = 0; kc < HIDDEN; kc += GBK) {
        #pragma unroll
        for (int p = 0; p < 4; ++p) {
            int r = rr + 32 * p;
            float4 v = *reinterpret_cast<const float4*>(
                &A[(size_t)(rb + r) * HIDDEN + kc + k4]);
            *reinterpret_cast<float4*>(&As[r * ASTR + k4]) = v;
        }
        #pragma unroll
        for (int p = 0; p < 2; ++p) {
            int c = rr + 32 * p;
            float4 v = *reinterpret_cast<const float4*>(
                &W_out[(size_t)(cb + c) * HIDDEN + kc + k4]);
            Bs[(k4 + 0) * BSTR + c] = v.x;
            Bs[(k4 + 1) * BSTR + c] = v.y;
            Bs[(k4 + 2) * BSTR + c] = v.z;
            Bs[(k4 + 3) * BSTR + c] = v.w;
        }
        __syncthreads();

        #pragma unroll 8
        for (int k = 0; k < GBK; ++k) {
            float a0 = As[(tr * 8 + 0) * ASTR + k];
            float a1 = As[(tr * 8 + 1) * ASTR + k];
            float a2 = As[(tr * 8 + 2) * ASTR + k];
            float a3 = As[(tr * 8 + 3) * ASTR + k];
            float a4 = As[(tr * 8 + 4) * ASTR + k];
            float a5 = As[(tr * 8 + 5) * ASTR + k];
            float a6 = As[(tr * 8 + 6) * ASTR + k];
            float a7 = As[(tr * 8 + 7) * ASTR + k];
            float4 bf = *reinterpret_cast<const float4*>(&Bs[k * BSTR + tc * 4]);

            ull aa0 = pack2(a0, a1), aa1 = pack2(a2, a3);
            ull aa2 = pack2(a4, a5), aa3 = pack2(a6, a7);
            ull bp0 = pack2(bf.x, bf.x), bp1 = pack2(bf.y, bf.y);
            ull bp2 = pack2(bf.z, bf.z), bp3 = pack2(bf.w, bf.w);

            ffma2(acc[ 0], aa0, bp0); ffma2(acc[ 1], aa0, bp1);
            ffma2(acc[ 2], aa0, bp2); ffma2(acc[ 3], aa0, bp3);
            ffma2(acc[ 4], aa1, bp0); ffma2(acc[ 5], aa1, bp1);
            ffma2(acc[ 6], aa1, bp2); ffma2(acc[ 7], aa1, bp3);
            ffma2(acc[ 8], aa2, bp0); ffma2(acc[ 9], aa2, bp1);
            ffma2(acc[10], aa2, bp2); ffma2(acc[11], aa2, bp3);
            ffma2(acc[12], aa3, bp0); ffma2(acc[13], aa3, bp1);
            ffma2(acc[14], aa3, bp2); ffma2(acc[15], aa3, bp3);
        }
        __syncthreads();
    }

    float4 bias4 = *reinterpret_cast<const float4*>(&b_out[cb + tc * 4]);
    #pragma unroll
    for (int ii = 0; ii < 4; ++ii) {
        float2 u0 = unpack2(acc[ii * 4 + 0]);
        float2 u1 = unpack2(acc[ii * 4 + 1]);
        float2 u2 = unpack2(acc[ii * 4 + 2]);
        float2 u3 = unpack2(acc[ii * 4 + 3]);
        int row = rb + tr * 8 + 2 * ii;
        float4 o0 = make_float4(u0.x + bias4.x, u1.x + bias4.y,
                                u2.x + bias4.z, u3.x + bias4.w);
        float4 o1 = make_float4(u0.y + bias4.x, u1.y + bias4.y,
                                u2.y + bias4.z, u3.y + bias4.w);
        *reinterpret_cast<float4*>(&C[(size_t)row * VOCAB + cb + tc * 4])       = o0;
        *reinterpret_cast<float4*>(&C[(size_t)(row + 1) * VOCAB + cb + tc * 4]) = o1;
    }
}

// ---------------- launch ---------------------------------------------------
extern "C" void kernel_launch(void* const* d_in, const int* in_sizes, int n_in,
                              void* d_out, int out_size)
{
    const int*   X     = (const int*)  d_in[0];
    const float* h0    = (const float*)d_in[1];
    const float* W_ih  = (const float*)d_in[2];
    const float* b_ih  = (const float*)d_in[3];
    const float* W_hh  = (const float*)d_in[4];
    const float* b_hh  = (const float*)d_in[5];
    const float* W_out = (const float*)d_in[6];
    const float* b_out = (const float*)d_in[7];
    float* out = (float*)d_out;

    // Second output (h_last) lives right after the main logits block, if the
    // harness buffer includes it.
    int write_hlast = (out_size >= OUT_MAIN + BATCH * HIDDEN) ? 1 : 0;
    float* hlast = out + OUT_MAIN;

    prep_kernel<<<16, 1024>>>(W_hh);
    rnn_kernel<<<BATCH, 1024>>>(X, h0, W_ih, b_ih, b_hh, hlast, write_hlast);
    gemm_kernel<<<dim3(VOCAB / GBN, (SEQ * BATCH) / GBM), 256>>>(W_out, b_out, out);
}

// round 6
// speedup vs baseline: 2.5750x; 2.5750x over previous
#include <cuda_runtime.h>
#include <cuda_bf16.h>
#include <cstdint>

#define VOCAB  8000
#define HIDDEN 256
#define BATCH  32
#define SEQ    256
#define OUT_MAIN (SEQ * BATCH * VOCAB)   // 65,536,000 floats

typedef unsigned long long ull;

// ---------------- scratch (__device__ globals: no allocs allowed) ----------
__device__ __align__(16) __nv_bfloat16 g_Y0[SEQ * BATCH * HIDDEN];  // bf16 hi of Y
__device__ __align__(16) __nv_bfloat16 g_Y1[SEQ * BATCH * HIDDEN];  // bf16 residual
__device__ __align__(16) __nv_bfloat16 g_W0[VOCAB * HIDDEN];        // bf16 hi of W_out
__device__ __align__(16) __nv_bfloat16 g_W1[VOCAB * HIDDEN];        // bf16 residual
__device__ float4 g_Wre[16 * 1024];                                 // W_hh thread-major

// ---------------- small PTX helpers ---------------------------------------
__device__ __forceinline__ void ffma2(ull& d, ull a, ull b) {
    asm("fma.rn.f32x2 %0, %1, %2, %0;" : "+l"(d) : "l"(a), "l"(b));
}
__device__ __forceinline__ float2 unpack2(ull v) {
    float2 r; asm("mov.b64 {%0, %1}, %2;" : "=f"(r.x), "=f"(r.y) : "l"(v)); return r;
}
union F4U { float4 f4; ulonglong2 u2; };

__device__ __forceinline__ uint32_t smem_u32(const void* p) {
    uint32_t a;
    asm("{ .reg .u64 t; cvta.to.shared.u64 t, %1; cvt.u32.u64 %0, t; }" : "=r"(a) : "l"(p));
    return a;
}
__device__ __forceinline__ void ldsm4(uint32_t* r, uint32_t addr) {
    asm volatile("ldmatrix.sync.aligned.m8n8.x4.shared.b16 {%0,%1,%2,%3}, [%4];"
                 : "=r"(r[0]), "=r"(r[1]), "=r"(r[2]), "=r"(r[3]) : "r"(addr));
}
__device__ __forceinline__ void mma16816(float* c, const uint32_t* a,
                                         uint32_t b0, uint32_t b1) {
    asm volatile(
        "mma.sync.aligned.m16n8k16.row.col.f32.bf16.bf16.f32 "
        "{%0,%1,%2,%3}, {%4,%5,%6,%7}, {%8,%9}, {%0,%1,%2,%3};"
        : "+f"(c[0]), "+f"(c[1]), "+f"(c[2]), "+f"(c[3])
        : "r"(a[0]), "r"(a[1]), "r"(a[2]), "r"(a[3]), "r"(b0), "r"(b1));
}

// ---------------- prep: W_hh reshuffle -------------------------------------
__global__ void prep_kernel(const float* __restrict__ W_hh) {
    int g   = blockIdx.x * blockDim.x + threadIdx.x;  // 0..16383
    int i   = g >> 10;
    int tid = g & 1023;
    int j   = tid & 255;
    int s   = tid >> 8;
    g_Wre[i * 1024 + tid] =
        *reinterpret_cast<const float4*>(&W_hh[j * HIDDEN + s * 64 + 4 * i]);
}

// ---------------- prep: W_out -> bf16 hi/lo --------------------------------
__global__ void prep_w_kernel(const float* __restrict__ W_out) {
    int i = blockIdx.x * blockDim.x + threadIdx.x;
    if (i < VOCAB * HIDDEN) {
        float w = W_out[i];
        __nv_bfloat16 w0 = __float2bfloat16(w);
        g_W0[i] = w0;
        g_W1[i] = __float2bfloat16(w - __bfloat162float(w0));
    }
}

// ---------------- recurrence (fused embedding gather) ----------------------
__global__ __launch_bounds__(1024, 1) void rnn_kernel(
    const int*   __restrict__ X,
    const float* __restrict__ h0,
    const float* __restrict__ W_ih,
    const float* __restrict__ b_ih,
    const float* __restrict__ b_hh,
    float*       __restrict__ hlast,
    int write_hlast)
{
    __shared__ __align__(16) float h_sh[HIDDEN];
    __shared__ float psum[4 * HIDDEN];
    __shared__ int   x_sh[SEQ];

    const int b   = blockIdx.x;
    const int tid = threadIdx.x;
    const int j   = tid & 255;
    const int s   = tid >> 8;

    float bias = 0.f;
    if (s == 0) bias = b_hh[j] + b_ih[j];
    if (tid < HIDDEN) h_sh[tid] = h0[b * HIDDEN + tid];
    if (tid < SEQ)    x_sh[tid] = X[b * SEQ + tid];
    __syncthreads();

    const float*  Wih_row = W_ih + (size_t)j * VOCAB;
    const float4* wre     = g_Wre + tid;

    for (int t = 0; t < SEQ; ++t) {
        float xv = 0.f;
        if (s == 0) xv = __ldg(&Wih_row[x_sh[t]]);

        ull acc = 0ULL;
        const ulonglong2* h2 = reinterpret_cast<const ulonglong2*>(h_sh + s * 64);
        #pragma unroll
        for (int i = 0; i < 16; ++i) {
            ulonglong2 hv = h2[i];          // broadcast LDS.128
            F4U u; u.f4 = wre[i * 1024];    // L1-resident LDG.128
            ffma2(acc, hv.x, u.u2.x);
            ffma2(acc, hv.y, u.u2.y);
        }
        float2 a2 = unpack2(acc);
        psum[s * HIDDEN + j] = a2.x + a2.y;
        __syncthreads();
        if (s == 0) {
            float v = psum[j] + psum[HIDDEN + j] + psum[2 * HIDDEN + j] +
                      psum[3 * HIDDEN + j] + xv + bias;
            float hn = tanhf(v);
            h_sh[j] = hn;
            size_t idx = (size_t)(t * BATCH + b) * HIDDEN + j;
            __nv_bfloat16 y0 = __float2bfloat16(hn);
            g_Y0[idx] = y0;
            g_Y1[idx] = __float2bfloat16(hn - __bfloat162float(y0));
        }
        __syncthreads();
    }
    if (write_hlast && tid < HIDDEN) hlast[b * HIDDEN + tid] = h_sh[tid];
}

// ---------------- HMMA GEMM: C = Y @ W_out^T + b_out ----------------------
// mma.sync m16n8k16 bf16, 3-term split: D = a0b0 + a0b1 + a1b0 (fp32 accum).
// CTA 128x128, BK=32, 8 warps (2 M x 4 N), warp tile 64x32.
#define BM 128
#define BN 128
#define BK 32
#define ASTR2 40   // smem row stride in bf16 (80B: ldmatrix-conflict-free)
#define NTILES ((VOCAB + BN - 1) / BN)   // 63

__shared__ __nv_bfloat16 sA0[BM * ASTR2];
__shared__ __nv_bfloat16 sA1[BM * ASTR2];
__shared__ __nv_bfloat16 sB0[BN * ASTR2];
__shared__ __nv_bfloat16 sB1[BN * ASTR2];

__device__ __forceinline__ void load_block(__nv_bfloat16* dst,
    const __nv_bfloat16* src, int row0, int rowmax, int kc, int tid)
{
    const uint4* s = reinterpret_cast<const uint4*>(src);
    #pragma unroll
    for (int p = 0; p < 2; ++p) {
        int q = tid + p * 256;
        int r = q >> 2, f = q & 3;               // r: tile row, f: 16B chunk
        int grow = row0 + r; if (grow > rowmax) grow = rowmax;
        uint4 v = s[(size_t)grow * (HIDDEN / 8) + (kc >> 3) + f];
        *reinterpret_cast<uint4*>(dst + r * ASTR2 + f * 8) = v;
    }
}

__global__ __launch_bounds__(256, 2) void gemm_kernel(
    const float* __restrict__ b_out,
    float*       __restrict__ C)
{
    const int tid  = threadIdx.x;
    const int lane = tid & 31;
    const int wid  = tid >> 5;
    const int wm   = wid & 1;        // 2 M-slices of 64
    const int wn   = wid >> 1;       // 4 N-slices of 32
    const int rb   = blockIdx.y * BM;
    const int cb   = blockIdx.x * BN;

    const uint32_t a0b = smem_u32(sA0), a1b = smem_u32(sA1);
    const uint32_t b0b = smem_u32(sB0), b1b = smem_u32(sB1);

    // per-lane ldmatrix address components
    const int arow = wm * 64 + (lane & 15);          // + ma*16
    const int acol = (lane >> 4) << 3;               // + kk
    const int brow = wn * 32 + (lane & 7) + ((lane >> 4) << 3);  // + pair*16
    const int bcol = ((lane >> 3) & 1) << 3;         // + kk

    float c[4][4][4];
    #pragma unroll
    for (int i = 0; i < 4; ++i)
        #pragma unroll
        for (int j = 0; j < 4; ++j)
            #pragma unroll
            for (int k = 0; k < 4; ++k) c[i][j][k] = 0.f;

    #pragma unroll 1
    for (int kc = 0; kc < HIDDEN; kc += BK) {
        load_block(sA0, g_Y0, rb, SEQ * BATCH - 1, kc, tid);
        load_block(sA1, g_Y1, rb, SEQ * BATCH - 1, kc, tid);
        load_block(sB0, g_W0, cb, VOCAB - 1, kc, tid);
        load_block(sB1, g_W1, cb, VOCAB - 1, kc, tid);
        __syncthreads();

        #pragma unroll
        for (int ks = 0; ks < 2; ++ks) {
            const int kk = ks * 16;
            const uint32_t aoff = (uint32_t)((arow * ASTR2 + kk + acol) * 2);
            const uint32_t boff = (uint32_t)((brow * ASTR2 + kk + bcol) * 2);

            uint32_t af[4][4], bf[2][4];
            #pragma unroll
            for (int ma = 0; ma < 4; ++ma)
                ldsm4(af[ma], a0b + aoff + (uint32_t)(ma * 16 * ASTR2 * 2));
            #pragma unroll
            for (int p = 0; p < 2; ++p)
                ldsm4(bf[p], b0b + boff + (uint32_t)(p * 16 * ASTR2 * 2));

            // pass 1: a0 * b0
            #pragma unroll
            for (int ma = 0; ma < 4; ++ma)
                #pragma unroll
                for (int nb = 0; nb < 4; ++nb)
                    mma16816(c[ma][nb], af[ma],
                             bf[nb >> 1][(nb & 1) * 2], bf[nb >> 1][(nb & 1) * 2 + 1]);

            // pass 2: a0 * b1
            #pragma unroll
            for (int p = 0; p < 2; ++p)
                ldsm4(bf[p], b1b + boff + (uint32_t)(p * 16 * ASTR2 * 2));
            #pragma unroll
            for (int ma = 0; ma < 4; ++ma)
                #pragma unroll
                for (int nb = 0; nb < 4; ++nb)
                    mma16816(c[ma][nb], af[ma],
                             bf[nb >> 1][(nb & 1) * 2], bf[nb >> 1][(nb & 1) * 2 + 1]);

            // pass 3: a1 * b0
            #pragma unroll
            for (int ma = 0; ma < 4; ++ma)
                ldsm4(af[ma], a1b + aoff + (uint32_t)(ma * 16 * ASTR2 * 2));
            #pragma unroll
            for (int p = 0; p < 2; ++p)
                ldsm4(bf[p], b0b + boff + (uint32_t)(p * 16 * ASTR2 * 2));
            #pragma unroll
            for (int ma = 0; ma < 4; ++ma)
                #pragma unroll
                for (int nb = 0; nb < 4; ++nb)
                    mma16816(c[ma][nb], af[ma],
                             bf[nb >> 1][(nb & 1) * 2], bf[nb >> 1][(nb & 1) * 2 + 1]);
        }
        __syncthreads();
    }

    // Epilogue: direct float2 stores + bias
    const int g = lane >> 2, t4 = lane & 3;
    #pragma unroll
    for (int nb = 0; nb < 4; ++nb) {
        int col = cb + wn * 32 + nb * 8 + 2 * t4;
        if (col >= VOCAB) continue;
        float bx = __ldg(&b_out[col]);
        float by = __ldg(&b_out[col + 1]);
        #pragma unroll
        for (int ma = 0; ma < 4; ++ma) {
            int row = rb + wm * 64 + ma * 16 + g;
            float2 v0 = make_float2(c[ma][nb][0] + bx, c[ma][nb][1] + by);
            float2 v1 = make_float2(c[ma][nb][2] + bx, c[ma][nb][3] + by);
            *reinterpret_cast<float2*>(&C[(size_t)row * VOCAB + col])       = v0;
            *reinterpret_cast<float2*>(&C[(size_t)(row + 8) * VOCAB + col]) = v1;
        }
    }
}

// ---------------- launch ---------------------------------------------------
extern "C" void kernel_launch(void* const* d_in, const int* in_sizes, int n_in,
                              void* d_out, int out_size)
{
    const int*   X     = (const int*)  d_in[0];
    const float* h0    = (const float*)d_in[1];
    const float* W_ih  = (const float*)d_in[2];
    const float* b_ih  = (const float*)d_in[3];
    const float* W_hh  = (const float*)d_in[4];
    const float* b_hh  = (const float*)d_in[5];
    const float* W_out = (const float*)d_in[6];
    const float* b_out = (const float*)d_in[7];
    float* out = (float*)d_out;

    int write_hlast = (out_size >= OUT_MAIN + BATCH * HIDDEN) ? 1 : 0;
    float* hlast = out + OUT_MAIN;

    prep_kernel<<<16, 1024>>>(W_hh);
    prep_w_kernel<<<(VOCAB * HIDDEN + 1023) / 1024, 1024>>>(W_out);
    rnn_kernel<<<BATCH, 1024>>>(X, h0, W_ih, b_ih, b_hh, hlast, write_hlast);
    gemm_kernel<<<dim3(NTILES, (SEQ * BATCH) / BM), 256>>>(b_out, out);
}

// round 7
// speedup vs baseline: 4.0969x; 1.5910x over previous
#include <cuda_runtime.h>
#include <cuda_bf16.h>
#include <cstdint>

#define VOCAB  8000
#define HIDDEN 256
#define BATCH  32
#define SEQ    256
#define OUT_MAIN (SEQ * BATCH * VOCAB)   // 65,536,000 floats

typedef unsigned long long ull;

// ---------------- scratch (__device__ globals: no allocs allowed) ----------
__device__ __align__(16) __nv_bfloat16 g_Y0[SEQ * BATCH * HIDDEN];  // bf16 hi of Y
__device__ __align__(16) __nv_bfloat16 g_Y1[SEQ * BATCH * HIDDEN];  // bf16 residual
__device__ __align__(16) __nv_bfloat16 g_W0[VOCAB * HIDDEN];        // bf16 hi of W_out
__device__ __align__(16) __nv_bfloat16 g_W1[VOCAB * HIDDEN];        // bf16 residual

// ---------------- small PTX helpers ---------------------------------------
__device__ __forceinline__ void ffma2(ull& d, ull a, ull b) {
    asm("fma.rn.f32x2 %0, %1, %2, %0;" : "+l"(d) : "l"(a), "l"(b));
}
__device__ __forceinline__ float2 unpack2(ull v) {
    float2 r; asm("mov.b64 {%0, %1}, %2;" : "=f"(r.x), "=f"(r.y) : "l"(v)); return r;
}
union F4U { float4 f4; ulonglong2 u2; };

__device__ __forceinline__ uint32_t smem_u32(const void* p) {
    uint32_t a;
    asm("{ .reg .u64 t; cvta.to.shared.u64 t, %1; cvt.u32.u64 %0, t; }" : "=r"(a) : "l"(p));
    return a;
}
__device__ __forceinline__ void ldsm4(uint32_t* r, uint32_t addr) {
    asm volatile("ldmatrix.sync.aligned.m8n8.x4.shared.b16 {%0,%1,%2,%3}, [%4];"
                 : "=r"(r[0]), "=r"(r[1]), "=r"(r[2]), "=r"(r[3]) : "r"(addr));
}
__device__ __forceinline__ void mma16816(float* c, const uint32_t* a,
                                         uint32_t b0, uint32_t b1) {
    asm volatile(
        "mma.sync.aligned.m16n8k16.row.col.f32.bf16.bf16.f32 "
        "{%0,%1,%2,%3}, {%4,%5,%6,%7}, {%8,%9}, {%0,%1,%2,%3};"
        : "+f"(c[0]), "+f"(c[1]), "+f"(c[2]), "+f"(c[3])
        : "r"(a[0]), "r"(a[1]), "r"(a[2]), "r"(a[3]), "r"(b0), "r"(b1));
}

// ---------------- prep: W_out -> bf16 hi/lo --------------------------------
__global__ void prep_w_kernel(const float* __restrict__ W_out) {
    int i = blockIdx.x * blockDim.x + threadIdx.x;
    if (i < VOCAB * HIDDEN) {
        float w = W_out[i];
        __nv_bfloat16 w0 = __float2bfloat16(w);
        g_W0[i] = w0;
        g_W1[i] = __float2bfloat16(w - __bfloat162float(w0));
    }
}

// ---------------- recurrence: 2-CTA cluster, W_hh register-resident --------
// 64 CTAs (2 per batch element), 512 threads each. Thread (j', s) owns
// W_hh rows j = rank*128 + j', k in [s*64, s*64+64) -> 64 floats in regs.
// Per step: LDS-broadcast h, 32 packed ffma2, smem reduce, tanh by 128
// threads, local + DSMEM peer write of new h (double-buffered), one
// cluster barrier.
__global__ __launch_bounds__(512, 1) __cluster_dims__(2, 1, 1)
void rnn_kernel(
    const int*   __restrict__ X,
    const float* __restrict__ h0,
    const float* __restrict__ W_ih,
    const float* __restrict__ b_ih,
    const float* __restrict__ W_hh,
    const float* __restrict__ b_hh,
    float*       __restrict__ hlast,
    int write_hlast)
{
    __shared__ __align__(16) float h_sh[2][HIDDEN];
    __shared__ float psum[4][128];
    __shared__ int   x_sh[SEQ];

    const int cta  = blockIdx.x;
    const int b    = cta >> 1;
    const int rank = cta & 1;          // cluster rank (cluster dim 2 along x)
    const int tid  = threadIdx.x;
    const int jl   = tid & 127;        // local output row
    const int s    = tid >> 7;         // k-slice 0..3
    const int jg   = rank * 128 + jl;  // global output row

    // W_hh rows into registers (one-time, ~128KB per CTA)
    F4U w[16];
    const float4* wrow =
        reinterpret_cast<const float4*>(W_hh + (size_t)jg * HIDDEN + s * 64);
    #pragma unroll
    for (int i = 0; i < 16; ++i) w[i].f4 = wrow[i];

    float bias = 0.f;
    if (s == 0) bias = b_hh[jg] + b_ih[jg];
    if (tid < HIDDEN) h_sh[0][tid] = h0[b * HIDDEN + tid];
    if (tid < SEQ)    x_sh[tid]    = X[b * SEQ + tid];

    // peer smem window base for h_sh
    uint32_t remote_base;
    {
        uint32_t local_base = smem_u32(&h_sh[0][0]);
        asm("mapa.shared::cluster.u32 %0, %1, %2;"
            : "=r"(remote_base) : "r"(local_base), "r"(rank ^ 1));
    }
    const float* Wih_row = W_ih + (size_t)jg * VOCAB;

    asm volatile("barrier.cluster.arrive.aligned;" ::: "memory");
    asm volatile("barrier.cluster.wait.aligned;"   ::: "memory");

    #pragma unroll 1
    for (int t = 0; t < SEQ; ++t) {
        const int cur = t & 1, nxt = cur ^ 1;

        // embedding gather prefetch (L2-latency hidden by fma loop + reduce)
        float xv = 0.f;
        if (s == 0) xv = __ldg(&Wih_row[x_sh[t]]);

        ull a0 = 0ULL, a1 = 0ULL;
        const ulonglong2* h2 =
            reinterpret_cast<const ulonglong2*>(&h_sh[cur][s * 64]);
        #pragma unroll
        for (int i = 0; i < 16; i += 2) {
            ulonglong2 hva = h2[i];        // broadcast LDS.128
            ffma2(a0, hva.x, w[i].u2.x);
            ffma2(a0, hva.y, w[i].u2.y);
            ulonglong2 hvb = h2[i + 1];
            ffma2(a1, hvb.x, w[i + 1].u2.x);
            ffma2(a1, hvb.y, w[i + 1].u2.y);
        }
        float2 p0 = unpack2(a0), p1 = unpack2(a1);
        psum[s][jl] = (p0.x + p0.y) + (p1.x + p1.y);
        __syncthreads();

        if (s == 0) {
            float v = psum[0][jl] + psum[1][jl] + psum[2][jl] + psum[3][jl]
                    + xv + bias;
            float hn = tanhf(v);
            h_sh[nxt][jg] = hn;
            uint32_t raddr = remote_base + (uint32_t)((nxt * HIDDEN + jg) * 4);
            asm volatile("st.shared::cluster.f32 [%0], %1;"
                         :: "r"(raddr), "f"(hn) : "memory");
            size_t idx = (size_t)(t * BATCH + b) * HIDDEN + jg;
            __nv_bfloat16 y0 = __float2bfloat16(hn);
            g_Y0[idx] = y0;
            g_Y1[idx] = __float2bfloat16(hn - __bfloat162float(y0));
        }
        // one cluster barrier per step: release own writes, acquire peer's
        asm volatile("barrier.cluster.arrive.aligned;" ::: "memory");
        asm volatile("barrier.cluster.wait.aligned;"   ::: "memory");
    }

    if (write_hlast && s == 0)
        hlast[b * HIDDEN + jg] = h_sh[0][jg];   // SEQ even -> final h in buf 0
}

// ---------------- HMMA GEMM: C = Y @ W_out^T + b_out ----------------------
// mma.sync m16n8k16 bf16, 3-term split: D = a0b0 + a0b1 + a1b0 (fp32 accum).
// CTA 128x128, BK=32, 8 warps (2 M x 4 N), warp tile 64x32.
#define BM 128
#define BN 128
#define BK 32
#define ASTR2 40   // smem row stride in bf16 (80B: ldmatrix-conflict-free)
#define NTILES ((VOCAB + BN - 1) / BN)   // 63

__shared__ __nv_bfloat16 sA0[BM * ASTR2];
__shared__ __nv_bfloat16 sA1[BM * ASTR2];
__shared__ __nv_bfloat16 sB0[BN * ASTR2];
__shared__ __nv_bfloat16 sB1[BN * ASTR2];

__device__ __forceinline__ void load_block(__nv_bfloat16* dst,
    const __nv_bfloat16* src, int row0, int rowmax, int kc, int tid)
{
    const uint4* s = reinterpret_cast<const uint4*>(src);
    #pragma unroll
    for (int p = 0; p < 2; ++p) {
        int q = tid + p * 256;
        int r = q >> 2, f = q & 3;               // r: tile row, f: 16B chunk
        int grow = row0 + r; if (grow > rowmax) grow = rowmax;
        uint4 v = s[(size_t)grow * (HIDDEN / 8) + (kc >> 3) + f];
        *reinterpret_cast<uint4*>(dst + r * ASTR2 + f * 8) = v;
    }
}

__global__ __launch_bounds__(256, 2) void gemm_kernel(
    const float* __restrict__ b_out,
    float*       __restrict__ C)
{
    const int tid  = threadIdx.x;
    const int lane = tid & 31;
    const int wid  = tid >> 5;
    const int wm   = wid & 1;        // 2 M-slices of 64
    const int wn   = wid >> 1;       // 4 N-slices of 32
    const int rb   = blockIdx.y * BM;
    const int cb   = blockIdx.x * BN;

    const uint32_t a0b = smem_u32(sA0), a1b = smem_u32(sA1);
    const uint32_t b0b = smem_u32(sB0), b1b = smem_u32(sB1);

    // per-lane ldmatrix address components
    const int arow = wm * 64 + (lane & 15);          // + ma*16
    const int acol = (lane >> 4) << 3;               // + kk
    const int brow = wn * 32 + (lane & 7) + ((lane >> 4) << 3);  // + pair*16
    const int bcol = ((lane >> 3) & 1) << 3;         // + kk

    float c[4][4][4];
    #pragma unroll
    for (int i = 0; i < 4; ++i)
        #pragma unroll
        for (int j = 0; j < 4; ++j)
            #pragma unroll
            for (int k = 0; k < 4; ++k) c[i][j][k] = 0.f;

    #pragma unroll 1
    for (int kc = 0; kc < HIDDEN; kc += BK) {
        load_block(sA0, g_Y0, rb, SEQ * BATCH - 1, kc, tid);
        load_block(sA1, g_Y1, rb, SEQ * BATCH - 1, kc, tid);
        load_block(sB0, g_W0, cb, VOCAB - 1, kc, tid);
        load_block(sB1, g_W1, cb, VOCAB - 1, kc, tid);
        __syncthreads();

        #pragma unroll
        for (int ks = 0; ks < 2; ++ks) {
            const int kk = ks * 16;
            const uint32_t aoff = (uint32_t)((arow * ASTR2 + kk + acol) * 2);
            const uint32_t boff = (uint32_t)((brow * ASTR2 + kk + bcol) * 2);

            uint32_t af[4][4], bf[2][4];
            #pragma unroll
            for (int ma = 0; ma < 4; ++ma)
                ldsm4(af[ma], a0b + aoff + (uint32_t)(ma * 16 * ASTR2 * 2));
            #pragma unroll
            for (int p = 0; p < 2; ++p)
                ldsm4(bf[p], b0b + boff + (uint32_t)(p * 16 * ASTR2 * 2));

            // pass 1: a0 * b0
            #pragma unroll
            for (int ma = 0; ma < 4; ++ma)
                #pragma unroll
                for (int nb = 0; nb < 4; ++nb)
                    mma16816(c[ma][nb], af[ma],
                             bf[nb >> 1][(nb & 1) * 2], bf[nb >> 1][(nb & 1) * 2 + 1]);

            // pass 2: a0 * b1
            #pragma unroll
            for (int p = 0; p < 2; ++p)
                ldsm4(bf[p], b1b + boff + (uint32_t)(p * 16 * ASTR2 * 2));
            #pragma unroll
            for (int ma = 0; ma < 4; ++ma)
                #pragma unroll
                for (int nb = 0; nb < 4; ++nb)
                    mma16816(c[ma][nb], af[ma],
                             bf[nb >> 1][(nb & 1) * 2], bf[nb >> 1][(nb & 1) * 2 + 1]);

            // pass 3: a1 * b0
            #pragma unroll
            for (int ma = 0; ma < 4; ++ma)
                ldsm4(af[ma], a1b + aoff + (uint32_t)(ma * 16 * ASTR2 * 2));
            #pragma unroll
            for (int p = 0; p < 2; ++p)
                ldsm4(bf[p], b0b + boff + (uint32_t)(p * 16 * ASTR2 * 2));
            #pragma unroll
            for (int ma = 0; ma < 4; ++ma)
                #pragma unroll
                for (int nb = 0; nb < 4; ++nb)
                    mma16816(c[ma][nb], af[ma],
                             bf[nb >> 1][(nb & 1) * 2], bf[nb >> 1][(nb & 1) * 2 + 1]);
        }
        __syncthreads();
    }

    // Epilogue: direct float2 stores + bias
    const int g = lane >> 2, t4 = lane & 3;
    #pragma unroll
    for (int nb = 0; nb < 4; ++nb) {
        int col = cb + wn * 32 + nb * 8 + 2 * t4;
        if (col >= VOCAB) continue;
        float bx = __ldg(&b_out[col]);
        float by = __ldg(&b_out[col + 1]);
        #pragma unroll
        for (int ma = 0; ma < 4; ++ma) {
            int row = rb + wm * 64 + ma * 16 + g;
            float2 v0 = make_float2(c[ma][nb][0] + bx, c[ma][nb][1] + by);
            float2 v1 = make_float2(c[ma][nb][2] + bx, c[ma][nb][3] + by);
            *reinterpret_cast<float2*>(&C[(size_t)row * VOCAB + col])       = v0;
            *reinterpret_cast<float2*>(&C[(size_t)(row + 8) * VOCAB + col]) = v1;
        }
    }
}

// ---------------- launch ---------------------------------------------------
extern "C" void kernel_launch(void* const* d_in, const int* in_sizes, int n_in,
                              void* d_out, int out_size)
{
    const int*   X     = (const int*)  d_in[0];
    const float* h0    = (const float*)d_in[1];
    const float* W_ih  = (const float*)d_in[2];
    const float* b_ih  = (const float*)d_in[3];
    const float* W_hh  = (const float*)d_in[4];
    const float* b_hh  = (const float*)d_in[5];
    const float* W_out = (const float*)d_in[6];
    const float* b_out = (const float*)d_in[7];
    float* out = (float*)d_out;

    int write_hlast = (out_size >= OUT_MAIN + BATCH * HIDDEN) ? 1 : 0;
    float* hlast = out + OUT_MAIN;

    prep_w_kernel<<<(VOCAB * HIDDEN + 1023) / 1024, 1024>>>(W_out);
    rnn_kernel<<<BATCH * 2, 512>>>(X, h0, W_ih, b_ih, W_hh, b_hh,
                                   hlast, write_hlast);
    gemm_kernel<<<dim3(NTILES, (SEQ * BATCH) / BM), 256>>>(b_out, out);
}